// round 4
// baseline (speedup 1.0000x reference)
#include <cuda_runtime.h>
#include <cuda_bf16.h>
#include <cstdint>

#define NN 65536
#define DD 256
#define KK 2048
#define ZQ (NN*DD)
#define EPS 6.0e-3f
#define CAP 32

// device scratch
__device__ uint32_t g_embP[KK * 128];   // bf16 pairs, k-permuted for mma frags
__device__ float    g_sume[KK];
__device__ int      g_cand[NN * CAP];
__device__ int      g_cnt[NN];
__device__ int      g_idx[NN];
__device__ double   g_loss;

// ---------------------------------------------------------------------------
__device__ __forceinline__ unsigned encf(float f) {
    unsigned u = __float_as_uint(f);
    return (u & 0x80000000u) ? ~u : (u | 0x80000000u);
}
__device__ __forceinline__ float decf(unsigned k) {
    return (k & 0x80000000u) ? __uint_as_float(k ^ 0x80000000u)
                             : __uint_as_float(~k);
}
__device__ __forceinline__ void mma16816(float* c, uint32_t a0, uint32_t a1,
                                         uint32_t a2, uint32_t a3,
                                         uint32_t b0, uint32_t b1) {
    asm volatile(
        "mma.sync.aligned.m16n8k16.row.col.f32.bf16.bf16.f32 "
        "{%0,%1,%2,%3}, {%4,%5,%6,%7}, {%8,%9}, {%0,%1,%2,%3};"
        : "+f"(c[0]), "+f"(c[1]), "+f"(c[2]), "+f"(c[3])
        : "r"(a0), "r"(a1), "r"(a2), "r"(a3), "r"(b0), "r"(b1));
}
__device__ __forceinline__ void cpasync16(void* sdst, const void* gsrc) {
    unsigned s = (unsigned)__cvta_generic_to_shared(sdst);
    asm volatile("cp.async.cg.shared.global [%0], [%1], 16;" :: "r"(s), "l"(gsrc));
}
__device__ __forceinline__ int pidx(int k) {   // u32-pair index of orig even k
    return ((k >> 4) << 3) + (((k & 7) >> 1) << 1) + ((k >> 3) & 1);
}
__device__ __forceinline__ uint32_t pk2(float lo, float hi) {
    __nv_bfloat162 h = __floats2bfloat162_rn(lo, hi);
    return *reinterpret_cast<uint32_t*>(&h);
}

// ---------------------------------------------------------------------------
// prep: emb fp32 -> bf16 pairs, k-permuted:  g_embP[row][pidx(k)]
// ---------------------------------------------------------------------------
__global__ void prep_emb(const float* __restrict__ emb) {
    int id = blockIdx.x * 256 + threadIdx.x;   // 65536 ids
    int row = id >> 5;
    int k0 = (id & 31) * 8;
    const float* s = emb + (size_t)row * DD + k0;
    float4 f0 = *reinterpret_cast<const float4*>(s);
    float4 f1 = *reinterpret_cast<const float4*>(s + 4);
    uint32_t* d = g_embP + (size_t)row * 128;
    d[pidx(k0 + 0)] = pk2(f0.x, f0.y);
    d[pidx(k0 + 2)] = pk2(f0.z, f0.w);
    d[pidx(k0 + 4)] = pk2(f1.x, f1.y);
    d[pidx(k0 + 6)] = pk2(f1.z, f1.w);
}

// ---------------------------------------------------------------------------
// sum(emb^2) per code (sequential, reference rounding) + zero loss
// ---------------------------------------------------------------------------
__global__ void sume_kernel(const float* __restrict__ emb) {
    int j = blockIdx.x * 256 + threadIdx.x;
    if (j < KK) {
        const float* e = emb + (size_t)j * DD;
        float s = 0.f;
        for (int c = 0; c < DD; ++c) {
            float v = e[c];
            s = __fadd_rn(s, __fmul_rn(v, v));
        }
        g_sume[j] = s;
    }
    if (j == 0) g_loss = 0.0;
}

// ---------------------------------------------------------------------------
// assign: bf16 tensor-core scores + eps-window candidate collection
// CTA: 128 pixels x 2048 codes. 8 warps; warp w -> pixels w*16..w*16+15.
// smem: A[128][528B] | B[2][64][528B] | cand[128][32] | cnt[128] | minU[128]
// ---------------------------------------------------------------------------
#define ARS 528
#define OFF_B   67584
#define BBUF    33792
#define OFF_CAND 135168
#define OFF_CNT  151552
#define OFF_MIN  152064
#define ASMEM    152576

__global__ void __launch_bounds__(256, 1) assign_mma(const float* __restrict__ z) {
    extern __shared__ char sm[];
    int*      cand = (int*)(sm + OFF_CAND);
    int*      cnt  = (int*)(sm + OFF_CNT);
    unsigned* minU = (unsigned*)(sm + OFF_MIN);

    const int tid = threadIdx.x;
    const int w = tid >> 5, lane = tid & 31;
    const int g = lane >> 2, tg = lane & 3;
    const int blk = blockIdx.x;
    const int b = blk >> 3, pix0 = (blk & 7) << 7;
    const float* zb = z + ((size_t)b << 18) + pix0;

    if (tid < 128) { cnt[tid] = 0; minU[tid] = 0xFFFFFFFFu; }

    // ---- stage A: z -> bf16, k-permuted, A[pix][kpos] ----
    for (int cc = w; cc < DD; cc += 8) {
        float4 v = *reinterpret_cast<const float4*>(zb + ((size_t)cc << 10) + (lane << 2));
        int s2 = ((cc >> 4) << 4) + (((cc & 7) >> 1) << 2) + (((cc >> 3) & 1) << 1) + (cc & 1);
        char* base = sm + (size_t)(lane << 2) * ARS + s2 * 2;
        *(__nv_bfloat16*)(base)           = __float2bfloat16_rn(v.x);
        *(__nv_bfloat16*)(base + ARS)     = __float2bfloat16_rn(v.y);
        *(__nv_bfloat16*)(base + 2 * ARS) = __float2bfloat16_rn(v.z);
        *(__nv_bfloat16*)(base + 3 * ARS) = __float2bfloat16_rn(v.w);
    }

    // ---- stage B chunk 0 ----
    #pragma unroll
    for (int i = 0; i < 8; ++i) {
        int lin = i * 256 + tid, r = lin >> 5, c16 = lin & 31;
        cpasync16(sm + OFF_B + r * ARS + c16 * 16,
                  (const char*)g_embP + ((size_t)r << 9) + (c16 << 4));
    }
    asm volatile("cp.async.commit_group;" ::: "memory");
    asm volatile("cp.async.wait_group 0;" ::: "memory");
    __syncthreads();

    const int p0 = w * 16 + g, p1 = p0 + 8;
    const char* arow0 = sm + (size_t)p0 * ARS + tg * 8;
    const char* arow1 = sm + (size_t)p1 * ARS + tg * 8;

    for (int ci = 0; ci < 32; ++ci) {
        const int jc = ci << 6;
        // prefetch next B chunk into other buffer
        if (ci + 1 < 32) {
            #pragma unroll
            for (int i = 0; i < 8; ++i) {
                int lin = i * 256 + tid, r = lin >> 5, c16 = lin & 31;
                cpasync16(sm + OFF_B + ((ci + 1) & 1) * BBUF + r * ARS + c16 * 16,
                          (const char*)g_embP + ((size_t)(jc + 64 + r) << 9) + (c16 << 4));
            }
            asm volatile("cp.async.commit_group;" ::: "memory");
        }
        const char* Bb = sm + OFF_B + (ci & 1) * BBUF + tg * 8;

        float acc[8][4];
        #pragma unroll
        for (int nt = 0; nt < 8; ++nt)
            #pragma unroll
            for (int e = 0; e < 4; ++e) acc[nt][e] = 0.f;

        #pragma unroll 4
        for (int kt = 0; kt < 16; ++kt) {
            uint2 aA = *reinterpret_cast<const uint2*>(arow0 + kt * 32);
            uint2 aB = *reinterpret_cast<const uint2*>(arow1 + kt * 32);
            #pragma unroll
            for (int nt = 0; nt < 8; ++nt) {
                uint2 bb = *reinterpret_cast<const uint2*>(Bb + (nt * 8 + g) * ARS + kt * 32);
                mma16816(acc[nt], aA.x, aB.x, aA.y, aB.y, bb.x, bb.y);
            }
        }

        // epilogue pass 1: d = se - 2m, per-pixel chunk min
        float mn0 = __int_as_float(0x7f800000), mn1 = mn0;
        #pragma unroll
        for (int nt = 0; nt < 8; ++nt)
            #pragma unroll
            for (int e = 0; e < 2; ++e) {
                float se = __ldg(&g_sume[jc + nt * 8 + 2 * tg + e]);
                float d0 = fmaf(acc[nt][e],     -2.f, se);
                float d1 = fmaf(acc[nt][2 + e], -2.f, se);
                acc[nt][e] = d0; acc[nt][2 + e] = d1;
                mn0 = fminf(mn0, d0); mn1 = fminf(mn1, d1);
            }
        mn0 = fminf(mn0, __shfl_xor_sync(~0u, mn0, 1));
        mn0 = fminf(mn0, __shfl_xor_sync(~0u, mn0, 2));
        mn1 = fminf(mn1, __shfl_xor_sync(~0u, mn1, 1));
        mn1 = fminf(mn1, __shfl_xor_sync(~0u, mn1, 2));
        if (tg == 0) {
            atomicMin(&minU[p0], encf(mn0));
            atomicMin(&minU[p1], encf(mn1));
        }
        __syncwarp();
        // pass 2: append candidates within EPS of running min
        float t0 = decf(minU[p0]) + EPS;
        float t1 = decf(minU[p1]) + EPS;
        #pragma unroll
        for (int nt = 0; nt < 8; ++nt)
            #pragma unroll
            for (int e = 0; e < 2; ++e) {
                int j = jc + nt * 8 + 2 * tg + e;
                if (acc[nt][e] <= t0) {
                    int ix = atomicAdd(&cnt[p0], 1);
                    if (ix < CAP) cand[p0 * CAP + ix] = j;
                }
                if (acc[nt][2 + e] <= t1) {
                    int ix = atomicAdd(&cnt[p1], 1);
                    if (ix < CAP) cand[p1 * CAP + ix] = j;
                }
            }

        asm volatile("cp.async.wait_group 0;" ::: "memory");
        __syncthreads();
    }

    // write candidate lists
    if (tid < 128) {
        int n = blk * 128 + tid;
        int c = cnt[tid];
        g_cnt[n] = c;
        if (c > CAP) c = CAP;
        for (int i = 0; i < c; ++i) g_cand[(size_t)n * CAP + i] = cand[tid * CAP + i];
    }
}

// ---------------------------------------------------------------------------
// refine: exact reference arithmetic on candidates only -> g_idx
// ---------------------------------------------------------------------------
__global__ void __launch_bounds__(256) refine_kernel(const float* __restrict__ z,
                                                     const float* __restrict__ emb) {
    const int n = blockIdx.x * 256 + threadIdx.x;
    const int b = n >> 10, pix = n & 1023;
    const size_t zbase = ((size_t)b << 18) + pix;
    const int cnt = g_cnt[n];
    float best = __int_as_float(0x7f800000);
    int   bi = 0x7fffffff;
    float sz = 0.f;

    if (cnt <= CAP) {
        for (int g0 = 0; g0 < cnt; g0 += 8) {
            int ids[8];
            #pragma unroll
            for (int i = 0; i < 8; ++i) {
                int q = g0 + i; if (q >= cnt) q = cnt - 1;
                ids[i] = g_cand[(size_t)n * CAP + q];
            }
            float m[8];
            #pragma unroll
            for (int i = 0; i < 8; ++i) m[i] = 0.f;
            for (int kc = 0; kc < 4; ++kc) {
                float zc[64];
                #pragma unroll
                for (int i = 0; i < 64; ++i)
                    zc[i] = __ldg(&z[zbase + ((size_t)(kc * 64 + i) << 10)]);
                if (g0 == 0)
                    #pragma unroll
                    for (int i = 0; i < 64; ++i)
                        sz = __fadd_rn(sz, __fmul_rn(zc[i], zc[i]));
                #pragma unroll
                for (int cd = 0; cd < 8; ++cd) {
                    const float4* ep = reinterpret_cast<const float4*>(
                        emb + (size_t)ids[cd] * DD + kc * 64);
                    float mm = m[cd];
                    #pragma unroll
                    for (int q = 0; q < 16; ++q) {
                        float4 e = __ldg(&ep[q]);
                        mm = fmaf(zc[q * 4 + 0], e.x, mm);
                        mm = fmaf(zc[q * 4 + 1], e.y, mm);
                        mm = fmaf(zc[q * 4 + 2], e.z, mm);
                        mm = fmaf(zc[q * 4 + 3], e.w, mm);
                    }
                    m[cd] = mm;
                }
            }
            #pragma unroll
            for (int cd = 0; cd < 8; ++cd) {
                if (g0 + cd < cnt) {
                    int j = ids[cd];
                    float d = fmaf(m[cd], -2.f, __fadd_rn(sz, __ldg(&g_sume[j])));
                    if (d < best || (d == best && j < bi)) { best = d; bi = j; }
                }
            }
        }
    } else {
        // overflow fallback: exact scan over all codes (expected unreachable)
        for (int c = 0; c < DD; ++c) {
            float v = __ldg(&z[zbase + ((size_t)c << 10)]);
            sz = __fadd_rn(sz, __fmul_rn(v, v));
        }
        for (int j = 0; j < KK; ++j) {
            float mm = 0.f;
            const float* ej = emb + (size_t)j * DD;
            for (int c = 0; c < DD; ++c)
                mm = fmaf(__ldg(&z[zbase + ((size_t)c << 10)]), __ldg(&ej[c]), mm);
            float d = fmaf(mm, -2.f, __fadd_rn(sz, __ldg(&g_sume[j])));
            if (d < best || (d == best && j < bi)) { best = d; bi = j; }
        }
    }
    g_idx[n] = bi;
}

// ---------------------------------------------------------------------------
// quant: gather + straight-through + loss, tiled 32 pixels x 256 dims
// ---------------------------------------------------------------------------
__global__ void __launch_bounds__(256) quant_kernel(const float* __restrict__ z,
                                                    const float* __restrict__ emb,
                                                    float* __restrict__ out) {
    __shared__ float es[32 * 257];
    __shared__ int   ids[32];
    __shared__ double ws[8];
    const int tid = threadIdx.x, w = tid >> 5, lane = tid & 31;
    const int n0 = blockIdx.x * 32;
    const int b = n0 >> 10, pl = n0 & 1023;

    if (tid < 32) ids[tid] = g_idx[n0 + tid];
    __syncthreads();
    #pragma unroll 4
    for (int r = 0; r < 32; ++r)
        es[r * 257 + tid] = __ldg(&emb[(size_t)ids[r] * DD + tid]);
    __syncthreads();

    const size_t base = ((size_t)b << 18) + pl + lane;
    double ls = 0.0;
    #pragma unroll 4
    for (int k = 0; k < 32; ++k) {
        int c = k * 8 + w;
        float zp = z[base + ((size_t)c << 10)];
        float e  = es[lane * 257 + c];
        float t  = __fsub_rn(e, zp);
        out[base + ((size_t)c << 10)] = __fadd_rn(zp, t);
        ls += (double)__fmul_rn(t, t);
    }
    #pragma unroll
    for (int off = 16; off; off >>= 1)
        ls += __shfl_down_sync(0xffffffffu, ls, off);
    if (lane == 0) ws[w] = ls;
    __syncthreads();
    if (tid == 0) {
        double t = 0.0;
        #pragma unroll
        for (int i = 0; i < 8; ++i) t += ws[i];
        atomicAdd(&g_loss, t);
    }
}

// ---------------------------------------------------------------------------
__global__ void write_extras_kernel(float* __restrict__ out, int out_size) {
    const int t = blockIdx.x * 256 + threadIdx.x;
    if (out_size == NN) { if (t < NN) out[t] = (float)g_idx[t]; return; }
    const int rem = out_size - ZQ;
    if (rem >= NN && t < NN) out[ZQ + t] = (float)g_idx[t];
    if (rem >= NN + 1 && t == 0) {
        float m = (float)(g_loss * (1.0 / 16777216.0));
        out[ZQ + NN] = __fadd_rn(m, __fmul_rn(0.25f, m));
    }
    if (rem >= 2 * NN + 1 && t < NN) out[ZQ + NN + 1 + t] = (float)g_idx[t];
}

// ---------------------------------------------------------------------------
extern "C" void kernel_launch(void* const* d_in, const int* in_sizes, int n_in,
                              void* d_out, int out_size) {
    const float* z;
    const float* emb;
    if (in_sizes[0] == ZQ) { z = (const float*)d_in[0]; emb = (const float*)d_in[1]; }
    else                   { z = (const float*)d_in[1]; emb = (const float*)d_in[0]; }
    float* out = (float*)d_out;

    cudaFuncSetAttribute(assign_mma,
                         cudaFuncAttributeMaxDynamicSharedMemorySize, ASMEM);

    prep_emb<<<256, 256>>>(emb);
    sume_kernel<<<8, 256>>>(emb);
    assign_mma<<<512, 256, ASMEM>>>(z);
    refine_kernel<<<256, 256>>>(z, emb);
    if (out_size >= ZQ)
        quant_kernel<<<NN / 32, 256>>>(z, emb, out);
    if (out_size > ZQ || out_size == NN)
        write_extras_kernel<<<NN / 256, 256>>>(out, out_size);
}

// round 6
// speedup vs baseline: 1.0891x; 1.0891x over previous
#include <cuda_runtime.h>
#include <cuda_bf16.h>
#include <cstdint>

#define NN 65536
#define DD 256
#define KK 2048
#define ZQ (NN*DD)
#define CAP 32

// ---------------------------------------------------------------------------
// device scratch
// ---------------------------------------------------------------------------
__device__ uint4  g_z8[512 * 2048];   // 16MB: [blk 512][kw 64][px 128] int8x4
__device__ uint4  g_e8[16 * 2048];    // 512KB: [chunk 16][kw 64][code 128]
__device__ float  g_sz[NN];           // per-pixel int8 scale
__device__ float  g_saz[NN];          // per-pixel sum |z|
__device__ float  g_se[KK];           // per-code int8 scale
__device__ float  g_sume[KK];         // exact sequential sum(e^2)
__device__ float  g_SEmax;            // max_j sum|e_j|
__device__ float  g_SEscale;          // max_j s_e
__device__ int    g_cand[NN * CAP];
__device__ int    g_cnt[NN];
__device__ int    g_idx[NN];
__device__ double g_loss;

// ---------------------------------------------------------------------------
// helpers
// ---------------------------------------------------------------------------
__device__ __forceinline__ unsigned encf(float f) {
    unsigned u = __float_as_uint(f);
    return (u & 0x80000000u) ? ~u : (u | 0x80000000u);
}
__device__ __forceinline__ float decf(unsigned k) {
    return (k & 0x80000000u) ? __uint_as_float(k ^ 0x80000000u)
                             : __uint_as_float(~k);
}
__device__ __forceinline__ void cpasync16(void* sdst, const void* gsrc) {
    unsigned s = (unsigned)__cvta_generic_to_shared(sdst);
    asm volatile("cp.async.cg.shared.global [%0], [%1], 16;" :: "r"(s), "l"(gsrc));
}
__device__ __forceinline__ void atomicMaxF(float* addr, float v) {
    atomicMax(reinterpret_cast<int*>(addr), __float_as_int(v));  // v >= 0
}

// ---------------------------------------------------------------------------
__global__ void init_kernel() {
    g_SEmax = 0.f; g_SEscale = 0.f; g_loss = 0.0;
}

// ---------------------------------------------------------------------------
// prep_e8: per-code int8 quant + exact sume + bound scalars
// ---------------------------------------------------------------------------
__global__ void prep_e8(const float* __restrict__ emb) {
    const int j = blockIdx.x * 256 + threadIdx.x;   // 8 x 256 = 2048
    const float* e = emb + (size_t)j * DD;

    // exact sequential sum(e^2) (reference rounding order)
    float s = 0.f;
    for (int c = 0; c < DD; ++c) {
        float v = e[c];
        s = __fadd_rn(s, __fmul_rn(v, v));
    }
    g_sume[j] = s;

    float mx = 0.f, sa = 0.f;
    for (int c = 0; c < DD; ++c) {
        float a = fabsf(e[c]);
        mx = fmaxf(mx, a);
        sa += a;
    }
    const float mxs = fmaxf(mx, 1e-30f);
    const float se  = mxs / 127.f;
    const float inv = 127.f / mxs;
    g_se[j] = se;
    atomicMaxF(&g_SEmax, sa * 1.0002f);
    atomicMaxF(&g_SEscale, se * 1.0002f);

    const int chunk = j >> 7, code = j & 127;
    uint32_t* dst = reinterpret_cast<uint32_t*>(g_e8) + (size_t)chunk * 8192 + code;
    for (int kw = 0; kw < 64; ++kw) {
        int q0 = max(-127, min(127, __float2int_rn(e[kw * 4 + 0] * inv)));
        int q1 = max(-127, min(127, __float2int_rn(e[kw * 4 + 1] * inv)));
        int q2 = max(-127, min(127, __float2int_rn(e[kw * 4 + 2] * inv)));
        int q3 = max(-127, min(127, __float2int_rn(e[kw * 4 + 3] * inv)));
        dst[kw * 128] = (uint32_t)(q0 & 0xFF) | ((uint32_t)(q1 & 0xFF) << 8)
                      | ((uint32_t)(q2 & 0xFF) << 16) | ((uint32_t)(q3 & 0xFF) << 24);
    }
}

// ---------------------------------------------------------------------------
// prep_z8: per-pixel int8 quant of z into GEMM layout
// block = 128 pixels (matches assign tiling)
// ---------------------------------------------------------------------------
__global__ void __launch_bounds__(256) prep_z8(const float* __restrict__ z) {
    __shared__ float m2[256], sa2[256], invs[128];
    const int tid = threadIdx.x, blk = blockIdx.x;
    const int b = blk >> 3, hw0 = (blk & 7) << 7;
    const float* zb = z + ((size_t)b << 18) + hw0;

    // pass 1: per-pixel maxabs + sum|z| (split dims across thread halves)
    {
        const int half = tid >> 7, px = tid & 127;
        float mx = 0.f, sa = 0.f;
        for (int i = 0; i < 128; ++i) {
            float v = zb[(size_t)(half * 128 + i) * 1024 + px];
            float a = fabsf(v);
            mx = fmaxf(mx, a);
            sa += a;
        }
        m2[tid] = mx; sa2[tid] = sa;
    }
    __syncthreads();
    if (tid < 128) {
        float mx = fmaxf(m2[tid], m2[tid + 128]);
        float sa = sa2[tid] + sa2[tid + 128];
        const float mxs = fmaxf(mx, 1e-30f);
        const int n = blk * 128 + tid;
        g_sz[n]  = mxs / 127.f;
        g_saz[n] = sa * 1.0002f;
        invs[tid] = 127.f / mxs;
    }
    __syncthreads();

    // pass 2: quantize + pack -> g_z8[blk][kw][px]
    const int px = tid & 127, kw0 = (tid >> 7) * 32;
    const float inv = invs[px];
    uint32_t* dst = reinterpret_cast<uint32_t*>(g_z8) + (size_t)blk * 8192 + px;
    for (int kw = kw0; kw < kw0 + 32; ++kw) {
        const int c0 = kw * 4;
        int q0 = max(-127, min(127, __float2int_rn(zb[(size_t)(c0 + 0) << 10 | px] * inv)));
        int q1 = max(-127, min(127, __float2int_rn(zb[(size_t)(c0 + 1) << 10 | px] * inv)));
        int q2 = max(-127, min(127, __float2int_rn(zb[(size_t)(c0 + 2) << 10 | px] * inv)));
        int q3 = max(-127, min(127, __float2int_rn(zb[(size_t)(c0 + 3) << 10 | px] * inv)));
        dst[kw * 128] = (uint32_t)(q0 & 0xFF) | ((uint32_t)(q1 & 0xFF) << 8)
                      | ((uint32_t)(q2 & 0xFF) << 16) | ((uint32_t)(q3 & 0xFF) << 24);
    }
}

// ---------------------------------------------------------------------------
// assign_dp4a: 128 pixels x 2048 codes per CTA, int8 dp4a GEMM +
// per-pixel eps-window candidate collection.
// smem: Z8 32KB | E8 2x32KB | SZ 512 | EPS 512 | cand 16KB | cnt 512 | min 512
// ---------------------------------------------------------------------------
#define OFF_Z8   0
#define OFF_E8   32768
#define OFF_SZ   98304
#define OFF_EPS  98816
#define OFF_CAND 99328
#define OFF_CNT  115712
#define OFF_MIN  116224
#define ASMEM    116736

__global__ void __launch_bounds__(256, 1) assign_dp4a() {
    extern __shared__ char sm[];
    uint32_t* Z8  = reinterpret_cast<uint32_t*>(sm + OFF_Z8);
    uint32_t* E8  = reinterpret_cast<uint32_t*>(sm + OFF_E8);
    float*    SZs = reinterpret_cast<float*>(sm + OFF_SZ);
    float*    EPSs= reinterpret_cast<float*>(sm + OFF_EPS);
    int*      cand= reinterpret_cast<int*>(sm + OFF_CAND);
    int*      cnt = reinterpret_cast<int*>(sm + OFF_CNT);
    unsigned* minU= reinterpret_cast<unsigned*>(sm + OFF_MIN);

    const int tid = threadIdx.x;
    const int tx = tid & 15, ty = tid >> 4;
    const int blk = blockIdx.x;

    // stage Z8 (32KB) + E8 chunk 0 (32KB)
    {
        const char* zs = reinterpret_cast<const char*>(g_z8) + (size_t)blk * 32768;
        const char* es = reinterpret_cast<const char*>(g_e8);
        #pragma unroll
        for (int i = 0; i < 8; ++i) {
            const int t = tid + i * 256;
            cpasync16(sm + OFF_Z8 + t * 16, zs + (size_t)t * 16);
            cpasync16(sm + OFF_E8 + t * 16, es + (size_t)t * 16);
        }
    }
    asm volatile("cp.async.commit_group;" ::: "memory");

    if (tid < 128) {
        const int n = blk * 128 + tid;
        const float sz = g_sz[n];
        const float B = 0.5f * sz * g_SEmax
                      + 0.5f * g_SEscale * (g_saz[n] + 128.f * sz);
        SZs[tid]  = sz;
        EPSs[tid] = 4.f * B + 2e-4f;
        cnt[tid] = 0;
        minU[tid] = 0xFFFFFFFFu;
    }
    asm volatile("cp.async.wait_group 0;" ::: "memory");
    __syncthreads();

    float szp[8], epsp[8];
    #pragma unroll
    for (int pi = 0; pi < 8; ++pi) {
        szp[pi]  = SZs[(ty << 3) + pi];
        epsp[pi] = EPSs[(ty << 3) + pi];
    }

    for (int ci = 0; ci < 16; ++ci) {
        // prefetch next E8 chunk into other buffer
        if (ci + 1 < 16) {
            const char* es = reinterpret_cast<const char*>(g_e8) + (size_t)(ci + 1) * 32768;
            char* dst = sm + OFF_E8 + ((ci + 1) & 1) * 32768;
            #pragma unroll
            for (int i = 0; i < 8; ++i) {
                const int t = tid + i * 256;
                cpasync16(dst + t * 16, es + (size_t)t * 16);
            }
        }
        asm volatile("cp.async.commit_group;" ::: "memory");

        const uint32_t* Bp = E8 + (ci & 1) * 8192;
        int acc[64];
        #pragma unroll
        for (int i = 0; i < 64; ++i) acc[i] = 0;

        #pragma unroll 8
        for (int kw = 0; kw < 64; ++kw) {
            int4 a0 = *reinterpret_cast<const int4*>(Z8 + (kw << 7) + (ty << 3));
            int4 a1 = *reinterpret_cast<const int4*>(Z8 + (kw << 7) + (ty << 3) + 4);
            int4 b0 = *reinterpret_cast<const int4*>(Bp + (kw << 7) + (tx << 3));
            int4 b1 = *reinterpret_cast<const int4*>(Bp + (kw << 7) + (tx << 3) + 4);
            const int a[8] = {a0.x, a0.y, a0.z, a0.w, a1.x, a1.y, a1.z, a1.w};
            const int b[8] = {b0.x, b0.y, b0.z, b0.w, b1.x, b1.y, b1.z, b1.w};
            #pragma unroll
            for (int pi = 0; pi < 8; ++pi)
                #pragma unroll
                for (int cj = 0; cj < 8; ++cj)
                    acc[pi * 8 + cj] = __dp4a(a[pi], b[cj], acc[pi * 8 + cj]);
        }

        // epilogue: d = se - 2*s_z*s_e*dot ; running per-pixel min
        const int jc = ci << 7;
        float q8[8], se8[8];
        #pragma unroll
        for (int cj = 0; cj < 8; ++cj) {
            const int j = jc + (tx << 3) + cj;
            se8[cj] = __ldg(&g_sume[j]);
            q8[cj]  = -2.f * __ldg(&g_se[j]);
        }
        float rmin[8];
        #pragma unroll
        for (int pi = 0; pi < 8; ++pi) rmin[pi] = __int_as_float(0x7f800000);
        #pragma unroll
        for (int cj = 0; cj < 8; ++cj)
            #pragma unroll
            for (int pi = 0; pi < 8; ++pi) {
                float t = (float)acc[pi * 8 + cj];
                float dd = fmaf(t * q8[cj], szp[pi], se8[cj]);
                rmin[pi] = fminf(rmin[pi], dd);
            }
        #pragma unroll
        for (int off = 1; off <= 8; off <<= 1)
            #pragma unroll
            for (int pi = 0; pi < 8; ++pi)
                rmin[pi] = fminf(rmin[pi], __shfl_xor_sync(0xffffffffu, rmin[pi], off));
        if (tx == 0) {
            #pragma unroll
            for (int pi = 0; pi < 8; ++pi)
                atomicMin(&minU[(ty << 3) + pi], encf(rmin[pi]));
        }
        __syncthreads();

        float thr[8];
        #pragma unroll
        for (int pi = 0; pi < 8; ++pi)
            thr[pi] = decf(minU[(ty << 3) + pi]) + epsp[pi];
        #pragma unroll
        for (int cj = 0; cj < 8; ++cj)
            #pragma unroll
            for (int pi = 0; pi < 8; ++pi) {
                float t = (float)acc[pi * 8 + cj];
                float dd = fmaf(t * q8[cj], szp[pi], se8[cj]);
                if (dd <= thr[pi]) {
                    const int p = (ty << 3) + pi;
                    int ix = atomicAdd(&cnt[p], 1);
                    if (ix < CAP) cand[p * CAP + ix] = jc + (tx << 3) + cj;
                }
            }

        asm volatile("cp.async.wait_group 0;" ::: "memory");
        __syncthreads();
    }

    if (tid < 128) {
        const int n = blk * 128 + tid;
        int c = cnt[tid];
        g_cnt[n] = c;
        if (c > CAP) c = CAP;
        for (int i = 0; i < c; ++i) g_cand[(size_t)n * CAP + i] = cand[tid * CAP + i];
    }
}

// ---------------------------------------------------------------------------
// refine: exact reference arithmetic on candidates only -> g_idx  (proven R3)
// ---------------------------------------------------------------------------
__global__ void __launch_bounds__(256) refine_kernel(const float* __restrict__ z,
                                                     const float* __restrict__ emb) {
    const int n = blockIdx.x * 256 + threadIdx.x;
    const int b = n >> 10, pix = n & 1023;
    const size_t zbase = ((size_t)b << 18) + pix;
    const int cnt = g_cnt[n];
    float best = __int_as_float(0x7f800000);
    int   bi = 0x7fffffff;
    float sz = 0.f;

    if (cnt <= CAP) {
        for (int g0 = 0; g0 < cnt; g0 += 8) {
            int ids[8];
            #pragma unroll
            for (int i = 0; i < 8; ++i) {
                int q = g0 + i; if (q >= cnt) q = cnt - 1;
                ids[i] = g_cand[(size_t)n * CAP + q];
            }
            float m[8];
            #pragma unroll
            for (int i = 0; i < 8; ++i) m[i] = 0.f;
            for (int kc = 0; kc < 4; ++kc) {
                float zc[64];
                #pragma unroll
                for (int i = 0; i < 64; ++i)
                    zc[i] = __ldg(&z[zbase + ((size_t)(kc * 64 + i) << 10)]);
                if (g0 == 0)
                    #pragma unroll
                    for (int i = 0; i < 64; ++i)
                        sz = __fadd_rn(sz, __fmul_rn(zc[i], zc[i]));
                #pragma unroll
                for (int cd = 0; cd < 8; ++cd) {
                    const float4* ep = reinterpret_cast<const float4*>(
                        emb + (size_t)ids[cd] * DD + kc * 64);
                    float mm = m[cd];
                    #pragma unroll
                    for (int q = 0; q < 16; ++q) {
                        float4 e = __ldg(&ep[q]);
                        mm = fmaf(zc[q * 4 + 0], e.x, mm);
                        mm = fmaf(zc[q * 4 + 1], e.y, mm);
                        mm = fmaf(zc[q * 4 + 2], e.z, mm);
                        mm = fmaf(zc[q * 4 + 3], e.w, mm);
                    }
                    m[cd] = mm;
                }
            }
            #pragma unroll
            for (int cd = 0; cd < 8; ++cd) {
                if (g0 + cd < cnt) {
                    int j = ids[cd];
                    float d = fmaf(m[cd], -2.f, __fadd_rn(sz, __ldg(&g_sume[j])));
                    if (d < best || (d == best && j < bi)) { best = d; bi = j; }
                }
            }
        }
    } else {
        for (int c = 0; c < DD; ++c) {
            float v = __ldg(&z[zbase + ((size_t)c << 10)]);
            sz = __fadd_rn(sz, __fmul_rn(v, v));
        }
        for (int j = 0; j < KK; ++j) {
            float mm = 0.f;
            const float* ej = emb + (size_t)j * DD;
            for (int c = 0; c < DD; ++c)
                mm = fmaf(__ldg(&z[zbase + ((size_t)c << 10)]), __ldg(&ej[c]), mm);
            float d = fmaf(mm, -2.f, __fadd_rn(sz, __ldg(&g_sume[j])));
            if (d < best || (d == best && j < bi)) { best = d; bi = j; }
        }
    }
    g_idx[n] = bi;
}

// ---------------------------------------------------------------------------
// quant: gather + straight-through + loss  (proven R3)
// ---------------------------------------------------------------------------
__global__ void __launch_bounds__(256) quant_kernel(const float* __restrict__ z,
                                                    const float* __restrict__ emb,
                                                    float* __restrict__ out) {
    __shared__ float es[32 * 257];
    __shared__ int   ids[32];
    __shared__ double ws[8];
    const int tid = threadIdx.x, w = tid >> 5, lane = tid & 31;
    const int n0 = blockIdx.x * 32;
    const int b = n0 >> 10, pl = n0 & 1023;

    if (tid < 32) ids[tid] = g_idx[n0 + tid];
    __syncthreads();
    #pragma unroll 4
    for (int r = 0; r < 32; ++r)
        es[r * 257 + tid] = __ldg(&emb[(size_t)ids[r] * DD + tid]);
    __syncthreads();

    const size_t base = ((size_t)b << 18) + pl + lane;
    double ls = 0.0;
    #pragma unroll 4
    for (int k = 0; k < 32; ++k) {
        int c = k * 8 + w;
        float zp = z[base + ((size_t)c << 10)];
        float e  = es[lane * 257 + c];
        float t  = __fsub_rn(e, zp);
        out[base + ((size_t)c << 10)] = __fadd_rn(zp, t);
        ls += (double)__fmul_rn(t, t);
    }
    #pragma unroll
    for (int off = 16; off; off >>= 1)
        ls += __shfl_down_sync(0xffffffffu, ls, off);
    if (lane == 0) ws[w] = ls;
    __syncthreads();
    if (tid == 0) {
        double t = 0.0;
        #pragma unroll
        for (int i = 0; i < 8; ++i) t += ws[i];
        atomicAdd(&g_loss, t);
    }
}

// ---------------------------------------------------------------------------
__global__ void write_extras_kernel(float* __restrict__ out, int out_size) {
    const int t = blockIdx.x * 256 + threadIdx.x;
    if (out_size == NN) { if (t < NN) out[t] = (float)g_idx[t]; return; }
    const int rem = out_size - ZQ;
    if (rem >= NN && t < NN) out[ZQ + t] = (float)g_idx[t];
    if (rem >= NN + 1 && t == 0) {
        float m = (float)(g_loss * (1.0 / 16777216.0));
        out[ZQ + NN] = __fadd_rn(m, __fmul_rn(0.25f, m));
    }
    if (rem >= 2 * NN + 1 && t < NN) out[ZQ + NN + 1 + t] = (float)g_idx[t];
}

// ---------------------------------------------------------------------------
extern "C" void kernel_launch(void* const* d_in, const int* in_sizes, int n_in,
                              void* d_out, int out_size) {
    const float* z;
    const float* emb;
    if (in_sizes[0] == ZQ) { z = (const float*)d_in[0]; emb = (const float*)d_in[1]; }
    else                   { z = (const float*)d_in[1]; emb = (const float*)d_in[0]; }
    float* out = (float*)d_out;

    cudaFuncSetAttribute(assign_dp4a,
                         cudaFuncAttributeMaxDynamicSharedMemorySize, ASMEM);

    init_kernel<<<1, 1>>>();
    prep_e8<<<8, 256>>>(emb);
    prep_z8<<<512, 256>>>(z);
    assign_dp4a<<<512, 256, ASMEM>>>();
    refine_kernel<<<256, 256>>>(z, emb);
    if (out_size >= ZQ)
        quant_kernel<<<NN / 32, 256>>>(z, emb, out);
    if (out_size > ZQ || out_size == NN)
        write_extras_kernel<<<NN / 256, 256>>>(out, out_size);
}

// round 7
// speedup vs baseline: 6.9765x; 6.4059x over previous
#include <cuda_runtime.h>
#include <cuda_bf16.h>
#include <cstdint>

#define NN 65536
#define DD 256
#define KK 2048
#define ZQ (NN*DD)
#define CAP 24
#define QMAX 16256.0f   // 127*128

// ---------------------------------------------------------------------------
// device scratch
// ---------------------------------------------------------------------------
__device__ uint32_t g_z16[1024 * 8192]; // 32MB: [blk 1024][kw 64][pair 2][px 64] int16x2
__device__ uint4    g_e8[16 * 2048];    // 512KB: [chunk 16][kw 64][code 128] int8x4
__device__ float    g_sz2[NN];          // per-pixel int15 scale
__device__ float    g_saz[NN];          // per-pixel sum|z| (with slack)
__device__ float    g_se[KK];           // per-code int8 scale
__device__ float    g_sume[KK];         // exact sequential sum(e^2)
__device__ float    g_SEmax;            // max_j sum|e_j| (with slack)
__device__ float    g_SEscale;          // max_j s_e (with slack)
__device__ int      g_cand[NN * CAP];
__device__ int      g_cnt[NN];
__device__ int      g_idx[NN];
__device__ double   g_loss;

// ---------------------------------------------------------------------------
// helpers
// ---------------------------------------------------------------------------
__device__ __forceinline__ unsigned encf(float f) {
    unsigned u = __float_as_uint(f);
    return (u & 0x80000000u) ? ~u : (u | 0x80000000u);
}
__device__ __forceinline__ float decf(unsigned k) {
    return (k & 0x80000000u) ? __uint_as_float(k ^ 0x80000000u)
                             : __uint_as_float(~k);
}
__device__ __forceinline__ void cpasync16(void* sdst, const void* gsrc) {
    unsigned s = (unsigned)__cvta_generic_to_shared(sdst);
    asm volatile("cp.async.cg.shared.global [%0], [%1], 16;" :: "r"(s), "l"(gsrc));
}
__device__ __forceinline__ void atomicMaxF(float* addr, float v) {
    atomicMax(reinterpret_cast<int*>(addr), __float_as_int(v));  // v >= 0
}
__device__ __forceinline__ uint32_t pk16(int a, int b) {
    return (uint32_t)((uint16_t)(int16_t)a) | ((uint32_t)((uint16_t)(int16_t)b) << 16);
}

// ---------------------------------------------------------------------------
__global__ void init_kernel() { g_SEmax = 0.f; g_SEscale = 0.f; g_loss = 0.0; }

// ---------------------------------------------------------------------------
// prep_e8: per-code int8 quant + exact sume + bound scalars (proven R5)
// ---------------------------------------------------------------------------
__global__ void prep_e8(const float* __restrict__ emb) {
    const int j = blockIdx.x * 256 + threadIdx.x;   // 2048
    const float* e = emb + (size_t)j * DD;

    float s = 0.f;
    for (int c = 0; c < DD; ++c) {
        float v = e[c];
        s = __fadd_rn(s, __fmul_rn(v, v));
    }
    g_sume[j] = s;

    float mx = 0.f, sa = 0.f;
    for (int c = 0; c < DD; ++c) {
        float a = fabsf(e[c]);
        mx = fmaxf(mx, a);
        sa += a;
    }
    const float mxs = fmaxf(mx, 1e-30f);
    const float se  = mxs / 127.f;
    const float inv = 127.f / mxs;
    g_se[j] = se;
    atomicMaxF(&g_SEmax, sa * 1.0002f);
    atomicMaxF(&g_SEscale, se * 1.0002f);

    const int chunk = j >> 7, code = j & 127;
    uint32_t* dst = reinterpret_cast<uint32_t*>(g_e8) + (size_t)chunk * 8192 + code;
    for (int kw = 0; kw < 64; ++kw) {
        int q0 = max(-127, min(127, __float2int_rn(e[kw * 4 + 0] * inv)));
        int q1 = max(-127, min(127, __float2int_rn(e[kw * 4 + 1] * inv)));
        int q2 = max(-127, min(127, __float2int_rn(e[kw * 4 + 2] * inv)));
        int q3 = max(-127, min(127, __float2int_rn(e[kw * 4 + 3] * inv)));
        dst[kw * 128] = (uint32_t)(q0 & 0xFF) | ((uint32_t)(q1 & 0xFF) << 8)
                      | ((uint32_t)(q2 & 0xFF) << 16) | ((uint32_t)(q3 & 0xFF) << 24);
    }
}

// ---------------------------------------------------------------------------
// prep_z16: per-pixel int15 quant of z; block = 64 pixels
// ---------------------------------------------------------------------------
__global__ void __launch_bounds__(256) prep_z16(const float* __restrict__ z) {
    __shared__ float m2[256], sa2[256], invs[64];
    const int tid = threadIdx.x, blk = blockIdx.x;     // 1024 blocks
    const int b = blk >> 4, hw0 = (blk & 15) << 6;
    const float* zb = z + ((size_t)b << 18) + hw0;
    const int px = tid & 63, seg = tid >> 6;           // 4 segs x 64 dims

    {
        float mx = 0.f, sa = 0.f;
        for (int i = 0; i < 64; ++i) {
            float v = zb[(size_t)(seg * 64 + i) * 1024 + px];
            float a = fabsf(v);
            mx = fmaxf(mx, a);
            sa += a;
        }
        m2[tid] = mx; sa2[tid] = sa;
    }
    __syncthreads();
    if (tid < 64) {
        float mx = fmaxf(fmaxf(m2[tid], m2[tid + 64]), fmaxf(m2[tid + 128], m2[tid + 192]));
        float sa = sa2[tid] + sa2[tid + 64] + sa2[tid + 128] + sa2[tid + 192];
        const float mxs = fmaxf(mx, 1e-30f);
        const int n = blk * 64 + tid;
        g_sz2[n] = mxs / QMAX;
        g_saz[n] = sa * 1.0002f;
        invs[tid] = QMAX / mxs;
    }
    __syncthreads();

    const float inv = invs[px];
    uint32_t* dst = g_z16 + (size_t)blk * 8192;
    for (int kw = seg * 16; kw < seg * 16 + 16; ++kw) {
        const int c0 = kw * 4;
        int q0 = max(-16256, min(16256, __float2int_rn(zb[(size_t)(c0 + 0) * 1024 + px] * inv)));
        int q1 = max(-16256, min(16256, __float2int_rn(zb[(size_t)(c0 + 1) * 1024 + px] * inv)));
        int q2 = max(-16256, min(16256, __float2int_rn(zb[(size_t)(c0 + 2) * 1024 + px] * inv)));
        int q3 = max(-16256, min(16256, __float2int_rn(zb[(size_t)(c0 + 3) * 1024 + px] * inv)));
        dst[kw * 128 + px]      = pk16(q0, q1);
        dst[kw * 128 + 64 + px] = pk16(q2, q3);
    }
}

// ---------------------------------------------------------------------------
// assign_dp2a: 64 pixels x 2048 codes per CTA. z int15 x e int8 via dp2a.
// smem: Z16 32K | E8 2x32K | SZ/EPS/MIN/CNT 1K | cand 6K   total 105472
// ---------------------------------------------------------------------------
#define OFF_Z    0
#define OFF_E    32768
#define OFF_SZ   98304
#define OFF_EPS  98560
#define OFF_MIN  98816
#define OFF_CNT  99072
#define OFF_CAND 99328
#define ASMEM    105472

__global__ void __launch_bounds__(256, 2) assign_dp2a() {
    extern __shared__ char sm[];
    const uint32_t* Z  = reinterpret_cast<const uint32_t*>(sm + OFF_Z);
    uint32_t* E        = reinterpret_cast<uint32_t*>(sm + OFF_E);
    float*    SZs      = reinterpret_cast<float*>(sm + OFF_SZ);
    float*    EPSs     = reinterpret_cast<float*>(sm + OFF_EPS);
    unsigned* minU     = reinterpret_cast<unsigned*>(sm + OFF_MIN);
    int*      cnt      = reinterpret_cast<int*>(sm + OFF_CNT);
    int*      cand     = reinterpret_cast<int*>(sm + OFF_CAND);

    const int tid = threadIdx.x;
    const int tx = tid & 15, ty = tid >> 4;   // tx: 8 codes, ty: 4 pixels
    const int blk = blockIdx.x;               // 1024

    // stage Z (32KB) + E chunk 0 (32KB)
    {
        const char* zs = reinterpret_cast<const char*>(g_z16) + (size_t)blk * 32768;
        const char* es = reinterpret_cast<const char*>(g_e8);
        #pragma unroll
        for (int i = 0; i < 8; ++i) {
            const int t = tid + i * 256;
            cpasync16(sm + OFF_Z + t * 16, zs + (size_t)t * 16);
            cpasync16(sm + OFF_E + t * 16, es + (size_t)t * 16);
        }
    }
    asm volatile("cp.async.commit_group;" ::: "memory");

    if (tid < 64) {
        const int n = blk * 64 + tid;
        const float sz2 = g_sz2[n];
        const float B = 0.5f * sz2 * g_SEmax
                      + 0.5f * g_SEscale * (g_saz[n] + 128.f * sz2);
        SZs[tid]  = sz2;
        EPSs[tid] = 4.f * B + 2e-4f;
        minU[tid] = 0xFFFFFFFFu;
        cnt[tid]  = 0;
    }
    asm volatile("cp.async.wait_group 0;" ::: "memory");
    __syncthreads();

    float szp[4], epsp[4];
    #pragma unroll
    for (int pi = 0; pi < 4; ++pi) {
        szp[pi]  = SZs[ty * 4 + pi];
        epsp[pi] = EPSs[ty * 4 + pi];
    }

    for (int ci = 0; ci < 16; ++ci) {
        // prefetch next E chunk into other buffer (overlaps with compute)
        if (ci + 1 < 16) {
            const char* es = reinterpret_cast<const char*>(g_e8) + (size_t)(ci + 1) * 32768;
            char* dst = sm + OFF_E + ((ci + 1) & 1) * 32768;
            #pragma unroll
            for (int i = 0; i < 8; ++i) {
                const int t = tid + i * 256;
                cpasync16(dst + t * 16, es + (size_t)t * 16);
            }
        }
        asm volatile("cp.async.commit_group;" ::: "memory");

        const uint32_t* Bp = E + (ci & 1) * 8192;
        int acc[32];
        #pragma unroll
        for (int i = 0; i < 32; ++i) acc[i] = 0;

        #pragma unroll 8
        for (int kw = 0; kw < 64; ++kw) {
            int4 a0 = *reinterpret_cast<const int4*>(Z + (kw << 7) + (ty << 2));       // pair0
            int4 a1 = *reinterpret_cast<const int4*>(Z + (kw << 7) + 64 + (ty << 2));  // pair1
            int4 b0 = *reinterpret_cast<const int4*>(Bp + (kw << 7) + (tx << 3));
            int4 b1 = *reinterpret_cast<const int4*>(Bp + (kw << 7) + (tx << 3) + 4);
            const int aa0[4] = {a0.x, a0.y, a0.z, a0.w};
            const int aa1[4] = {a1.x, a1.y, a1.z, a1.w};
            const int bb[8]  = {b0.x, b0.y, b0.z, b0.w, b1.x, b1.y, b1.z, b1.w};
            #pragma unroll
            for (int pi = 0; pi < 4; ++pi)
                #pragma unroll
                for (int cj = 0; cj < 8; ++cj) {
                    int a = __dp2a_lo(aa0[pi], bb[cj], acc[pi * 8 + cj]);
                    acc[pi * 8 + cj] = __dp2a_hi(aa1[pi], bb[cj], a);
                }
        }

        // epilogue: d = sume_j - 2*sz2*se_j*acc ; running per-pixel min
        const int jc = ci << 7;
        float q8[8], se8[8];
        #pragma unroll
        for (int cj = 0; cj < 8; ++cj) {
            const int j = jc + (tx << 3) + cj;
            se8[cj] = __ldg(&g_sume[j]);
            q8[cj]  = -2.f * __ldg(&g_se[j]);
        }
        float rmin[4];
        #pragma unroll
        for (int pi = 0; pi < 4; ++pi) rmin[pi] = __int_as_float(0x7f800000);
        #pragma unroll
        for (int cj = 0; cj < 8; ++cj)
            #pragma unroll
            for (int pi = 0; pi < 4; ++pi) {
                float dd = fmaf((float)acc[pi * 8 + cj] * q8[cj], szp[pi], se8[cj]);
                rmin[pi] = fminf(rmin[pi], dd);
            }
        #pragma unroll
        for (int off = 1; off <= 8; off <<= 1)
            #pragma unroll
            for (int pi = 0; pi < 4; ++pi)
                rmin[pi] = fminf(rmin[pi], __shfl_xor_sync(0xffffffffu, rmin[pi], off));
        if (tx == 0) {
            #pragma unroll
            for (int pi = 0; pi < 4; ++pi)
                atomicMin(&minU[ty * 4 + pi], encf(rmin[pi]));
        }
        __syncthreads();

        float thr[4];
        #pragma unroll
        for (int pi = 0; pi < 4; ++pi)
            thr[pi] = decf(minU[ty * 4 + pi]) + epsp[pi];
        #pragma unroll
        for (int cj = 0; cj < 8; ++cj)
            #pragma unroll
            for (int pi = 0; pi < 4; ++pi) {
                float dd = fmaf((float)acc[pi * 8 + cj] * q8[cj], szp[pi], se8[cj]);
                if (dd <= thr[pi]) {
                    const int p = ty * 4 + pi;
                    int ix = atomicAdd(&cnt[p], 1);
                    if (ix < CAP) cand[p * CAP + ix] = jc + (tx << 3) + cj;
                }
            }

        asm volatile("cp.async.wait_group 0;" ::: "memory");
        __syncthreads();
    }

    if (tid < 64) {
        const int n = blk * 64 + tid;
        int c = cnt[tid];
        g_cnt[n] = c;
        if (c > CAP) c = CAP;
        for (int i = 0; i < c; ++i) g_cand[(size_t)n * CAP + i] = cand[tid * CAP + i];
    }
}

// ---------------------------------------------------------------------------
// refine: exact reference arithmetic (sequential fp32) on candidates -> g_idx
// ---------------------------------------------------------------------------
__device__ __forceinline__ void dot8(const float* __restrict__ z,
                                     const float* __restrict__ emb,
                                     size_t zbase, const int* ids,
                                     float* m, float& sz, bool do_sz) {
    #pragma unroll
    for (int i = 0; i < 8; ++i) m[i] = 0.f;
    for (int kc = 0; kc < 4; ++kc) {
        float zc[64];
        #pragma unroll
        for (int i = 0; i < 64; ++i)
            zc[i] = __ldg(&z[zbase + ((size_t)(kc * 64 + i) << 10)]);
        if (do_sz)
            #pragma unroll
            for (int i = 0; i < 64; ++i)
                sz = __fadd_rn(sz, __fmul_rn(zc[i], zc[i]));
        #pragma unroll
        for (int cd = 0; cd < 8; ++cd) {
            const float4* ep = reinterpret_cast<const float4*>(
                emb + (size_t)ids[cd] * DD + kc * 64);
            float mm = m[cd];
            #pragma unroll
            for (int q = 0; q < 16; ++q) {
                float4 e = __ldg(&ep[q]);
                mm = fmaf(zc[q * 4 + 0], e.x, mm);
                mm = fmaf(zc[q * 4 + 1], e.y, mm);
                mm = fmaf(zc[q * 4 + 2], e.z, mm);
                mm = fmaf(zc[q * 4 + 3], e.w, mm);
            }
            m[cd] = mm;
        }
    }
}

__global__ void __launch_bounds__(256) refine_kernel(const float* __restrict__ z,
                                                     const float* __restrict__ emb) {
    const int n = blockIdx.x * 256 + threadIdx.x;
    const int b = n >> 10, pix = n & 1023;
    const size_t zbase = ((size_t)b << 18) + pix;
    const int cnt = g_cnt[n];
    float best = __int_as_float(0x7f800000);
    int   bi = 0x7fffffff;
    float sz = 0.f;
    float m[8];
    int ids[8];

    if (cnt <= CAP) {
        for (int g0 = 0; g0 < cnt; g0 += 8) {
            #pragma unroll
            for (int i = 0; i < 8; ++i) {
                int q = g0 + i; if (q >= cnt) q = cnt - 1;
                ids[i] = g_cand[(size_t)n * CAP + q];
            }
            dot8(z, emb, zbase, ids, m, sz, g0 == 0);
            #pragma unroll
            for (int cd = 0; cd < 8; ++cd) {
                if (g0 + cd < cnt) {
                    int j = ids[cd];
                    float d = fmaf(m[cd], -2.f, __fadd_rn(sz, __ldg(&g_sume[j])));
                    if (d < best || (d == best && j < bi)) { best = d; bi = j; }
                }
            }
        }
    } else {
        // overflow fallback: exact grouped scan over all codes (rare)
        for (int g0 = 0; g0 < KK; g0 += 8) {
            #pragma unroll
            for (int i = 0; i < 8; ++i) ids[i] = g0 + i;
            dot8(z, emb, zbase, ids, m, sz, g0 == 0);
            #pragma unroll
            for (int cd = 0; cd < 8; ++cd) {
                int j = g0 + cd;
                float d = fmaf(m[cd], -2.f, __fadd_rn(sz, __ldg(&g_sume[j])));
                if (d < best || (d == best && j < bi)) { best = d; bi = j; }
            }
        }
    }
    g_idx[n] = bi;
}

// ---------------------------------------------------------------------------
// quant: gather + straight-through + loss (proven exact)
// ---------------------------------------------------------------------------
__global__ void __launch_bounds__(256) quant_kernel(const float* __restrict__ z,
                                                    const float* __restrict__ emb,
                                                    float* __restrict__ out) {
    __shared__ float es[32 * 257];
    __shared__ int   ids[32];
    __shared__ double ws[8];
    const int tid = threadIdx.x, w = tid >> 5, lane = tid & 31;
    const int n0 = blockIdx.x * 32;
    const int b = n0 >> 10, pl = n0 & 1023;

    if (tid < 32) ids[tid] = g_idx[n0 + tid];
    __syncthreads();
    #pragma unroll 4
    for (int r = 0; r < 32; ++r)
        es[r * 257 + tid] = __ldg(&emb[(size_t)ids[r] * DD + tid]);
    __syncthreads();

    const size_t base = ((size_t)b << 18) + pl + lane;
    double ls = 0.0;
    #pragma unroll 4
    for (int k = 0; k < 32; ++k) {
        int c = k * 8 + w;
        float zp = z[base + ((size_t)c << 10)];
        float e  = es[lane * 257 + c];
        float t  = __fsub_rn(e, zp);
        out[base + ((size_t)c << 10)] = __fadd_rn(zp, t);
        ls += (double)__fmul_rn(t, t);
    }
    #pragma unroll
    for (int off = 16; off; off >>= 1)
        ls += __shfl_down_sync(0xffffffffu, ls, off);
    if (lane == 0) ws[w] = ls;
    __syncthreads();
    if (tid == 0) {
        double t = 0.0;
        #pragma unroll
        for (int i = 0; i < 8; ++i) t += ws[i];
        atomicAdd(&g_loss, t);
    }
}

// ---------------------------------------------------------------------------
__global__ void write_extras_kernel(float* __restrict__ out, int out_size) {
    const int t = blockIdx.x * 256 + threadIdx.x;
    if (out_size == NN) { if (t < NN) out[t] = (float)g_idx[t]; return; }
    const int rem = out_size - ZQ;
    if (rem >= NN && t < NN) out[ZQ + t] = (float)g_idx[t];
    if (rem >= NN + 1 && t == 0) {
        float m = (float)(g_loss * (1.0 / 16777216.0));
        out[ZQ + NN] = __fadd_rn(m, __fmul_rn(0.25f, m));
    }
    if (rem >= 2 * NN + 1 && t < NN) out[ZQ + NN + 1 + t] = (float)g_idx[t];
}

// ---------------------------------------------------------------------------
extern "C" void kernel_launch(void* const* d_in, const int* in_sizes, int n_in,
                              void* d_out, int out_size) {
    const float* z;
    const float* emb;
    if (in_sizes[0] == ZQ) { z = (const float*)d_in[0]; emb = (const float*)d_in[1]; }
    else                   { z = (const float*)d_in[1]; emb = (const float*)d_in[0]; }
    float* out = (float*)d_out;

    cudaFuncSetAttribute(assign_dp2a,
                         cudaFuncAttributeMaxDynamicSharedMemorySize, ASMEM);

    init_kernel<<<1, 1>>>();
    prep_e8<<<8, 256>>>(emb);
    prep_z16<<<1024, 256>>>(z);
    assign_dp2a<<<1024, 256, ASMEM>>>();
    refine_kernel<<<256, 256>>>(z, emb);
    if (out_size >= ZQ)
        quant_kernel<<<NN / 32, 256>>>(z, emb, out);
    if (out_size > ZQ || out_size == NN)
        write_extras_kernel<<<NN / 256, 256>>>(out, out_size);
}

// round 8
// speedup vs baseline: 14.4671x; 2.0737x over previous
#include <cuda_runtime.h>
#include <cuda_bf16.h>
#include <cstdint>

#define NN 65536
#define DD 256
#define KK 2048
#define ZQ (NN*DD)
#define CAP 48
#define QMAX 16256.0f   // 127*128

// ---------------------------------------------------------------------------
// device scratch
// ---------------------------------------------------------------------------
__device__ uint4    g_e8[16 * 2048];    // 512KB: [chunk 16][kw 64][code 128] int8x4
__device__ float    g_se[KK];           // per-code int8 scale
__device__ float    g_sume[KK];         // exact sequential sum(e^2)
__device__ float    g_SEmax;            // max_j sum|e_j| (with slack)
__device__ float    g_SEscale;          // max_j s_e (with slack)
__device__ float    g_zmax;             // global max|z|
__device__ int      g_cand[NN * CAP];
__device__ int      g_cnt[NN];
__device__ int      g_idx[NN];
__device__ double   g_loss;

// ---------------------------------------------------------------------------
// helpers
// ---------------------------------------------------------------------------
__device__ __forceinline__ unsigned encf(float f) {
    unsigned u = __float_as_uint(f);
    return (u & 0x80000000u) ? ~u : (u | 0x80000000u);
}
__device__ __forceinline__ float decf(unsigned k) {
    return (k & 0x80000000u) ? __uint_as_float(k ^ 0x80000000u)
                             : __uint_as_float(~k);
}
__device__ __forceinline__ void cpasync16(void* sdst, const void* gsrc) {
    unsigned s = (unsigned)__cvta_generic_to_shared(sdst);
    asm volatile("cp.async.cg.shared.global [%0], [%1], 16;" :: "r"(s), "l"(gsrc));
}
__device__ __forceinline__ void atomicMaxF(float* addr, float v) {
    atomicMax(reinterpret_cast<int*>(addr), __float_as_int(v));  // v >= 0
}
__device__ __forceinline__ uint32_t pk16(int a, int b) {
    return (uint32_t)((uint16_t)(int16_t)a) | ((uint32_t)((uint16_t)(int16_t)b) << 16);
}

// ---------------------------------------------------------------------------
__global__ void init_kernel() {
    g_SEmax = 0.f; g_SEscale = 0.f; g_zmax = 0.f; g_loss = 0.0;
}

// ---------------------------------------------------------------------------
// zmax: global max|z| (grid-stride, float4)
// ---------------------------------------------------------------------------
__global__ void __launch_bounds__(256) zmax_kernel(const float* __restrict__ z) {
    const int t = blockIdx.x * 256 + threadIdx.x;   // 262144 threads
    const float4* z4 = reinterpret_cast<const float4*>(z);
    float mx = 0.f;
    #pragma unroll 4
    for (int i = 0; i < 16; ++i) {
        float4 v = __ldg(&z4[(size_t)t * 16 + i]);
        mx = fmaxf(mx, fmaxf(fmaxf(fabsf(v.x), fabsf(v.y)),
                             fmaxf(fabsf(v.z), fabsf(v.w))));
    }
    #pragma unroll
    for (int off = 16; off; off >>= 1)
        mx = fmaxf(mx, __shfl_xor_sync(0xffffffffu, mx, off));
    if ((threadIdx.x & 31) == 0) atomicMaxF(&g_zmax, mx);
}

// ---------------------------------------------------------------------------
// prep_e8: per-code int8 quant + exact sume + bound scalars (proven)
// ---------------------------------------------------------------------------
__global__ void prep_e8(const float* __restrict__ emb) {
    const int j = blockIdx.x * 256 + threadIdx.x;   // 2048
    const float* e = emb + (size_t)j * DD;

    float s = 0.f;
    for (int c = 0; c < DD; ++c) {
        float v = e[c];
        s = __fadd_rn(s, __fmul_rn(v, v));
    }
    g_sume[j] = s;

    float mx = 0.f, sa = 0.f;
    for (int c = 0; c < DD; ++c) {
        float a = fabsf(e[c]);
        mx = fmaxf(mx, a);
        sa += a;
    }
    const float mxs = fmaxf(mx, 1e-30f);
    const float se  = mxs / 127.f;
    const float inv = 127.f / mxs;
    g_se[j] = se;
    atomicMaxF(&g_SEmax, sa * 1.0005f);
    atomicMaxF(&g_SEscale, se * 1.0005f);

    const int chunk = j >> 7, code = j & 127;
    uint32_t* dst = reinterpret_cast<uint32_t*>(g_e8) + (size_t)chunk * 8192 + code;
    for (int kw = 0; kw < 64; ++kw) {
        int q0 = max(-127, min(127, __float2int_rn(e[kw * 4 + 0] * inv)));
        int q1 = max(-127, min(127, __float2int_rn(e[kw * 4 + 1] * inv)));
        int q2 = max(-127, min(127, __float2int_rn(e[kw * 4 + 2] * inv)));
        int q3 = max(-127, min(127, __float2int_rn(e[kw * 4 + 3] * inv)));
        dst[kw * 128] = (uint32_t)(q0 & 0xFF) | ((uint32_t)(q1 & 0xFF) << 8)
                      | ((uint32_t)(q2 & 0xFF) << 16) | ((uint32_t)(q3 & 0xFF) << 24);
    }
}

// ---------------------------------------------------------------------------
// assign_dp2a: 64 pixels x 2048 codes per CTA; z quantized in-kernel (global
// scale, int15) into smem; e int8 chunks double-buffered; dp2a GEMM +
// eps-window candidate collection.
// smem layout:
//   Z16   @0       32768
//   E8    @32768   65536 (2 x 32KB)
//   cand  @98304   12288 (64 x 48 int)
//   saz   @110592  256
//   eps   @110848  256
//   minU  @111104  256
//   cnt   @111360  256        total 111616
// ---------------------------------------------------------------------------
#define OFF_Z    0
#define OFF_E    32768
#define OFF_CAND 98304
#define OFF_SAZ  110592
#define OFF_EPS  110848
#define OFF_MIN  111104
#define OFF_CNT  111360
#define ASMEM    111616

__global__ void __launch_bounds__(256, 2) assign_dp2a(const float* __restrict__ z) {
    extern __shared__ char sm[];
    uint32_t* Z        = reinterpret_cast<uint32_t*>(sm + OFF_Z);
    uint32_t* E        = reinterpret_cast<uint32_t*>(sm + OFF_E);
    int*      cand     = reinterpret_cast<int*>(sm + OFF_CAND);
    float*    sazs     = reinterpret_cast<float*>(sm + OFF_SAZ);
    float*    epss     = reinterpret_cast<float*>(sm + OFF_EPS);
    unsigned* minU     = reinterpret_cast<unsigned*>(sm + OFF_MIN);
    int*      cnt      = reinterpret_cast<int*>(sm + OFF_CNT);

    const int tid = threadIdx.x;
    const int tx = tid & 15, ty = tid >> 4;   // tx: 8 codes, ty: 4 pixels
    const int blk = blockIdx.x;               // 1024
    const int b = blk >> 4, px0 = (blk & 15) << 6;
    const float* zb = z + ((size_t)b << 18) + px0;

    // E chunk 0 prefetch
    {
        const char* es = reinterpret_cast<const char*>(g_e8);
        #pragma unroll
        for (int i = 0; i < 8; ++i) {
            const int t = tid + i * 256;
            cpasync16(sm + OFF_E + t * 16, es + (size_t)t * 16);
        }
    }
    asm volatile("cp.async.commit_group;" ::: "memory");

    if (tid < 64) { sazs[tid] = 0.f; minU[tid] = 0xFFFFFFFFu; cnt[tid] = 0; }
    __syncthreads();

    // ---- in-kernel z quantization (global int15 scale) ----
    const float zmx = fmaxf(g_zmax, 1e-30f);
    const float invq = QMAX / zmx;
    const int px = tid & 63;
    {
        float myabs = 0.f;
        #pragma unroll 4
        for (int it = 0; it < 32; ++it) {
            const int cpair = (tid >> 6) + (it << 2);   // 0..127
            const int c = cpair * 2;
            float v0 = __ldg(&zb[((size_t)c << 10) + px]);
            float v1 = __ldg(&zb[((size_t)(c + 1) << 10) + px]);
            myabs += fabsf(v0) + fabsf(v1);
            int q0 = max(-16256, min(16256, __float2int_rn(v0 * invq)));
            int q1 = max(-16256, min(16256, __float2int_rn(v1 * invq)));
            const int kw = cpair >> 1, pair = cpair & 1;
            Z[(kw << 7) + (pair << 6) + px] = pk16(q0, q1);
        }
        atomicAdd(&sazs[px], myabs);
    }
    __syncthreads();

    const float szg = zmx / QMAX;
    if (tid < 64) {
        const float B = 0.5f * szg * g_SEmax
                      + 0.5f * g_SEscale * (sazs[tid] * 1.0005f + 128.f * szg);
        epss[tid] = 4.f * B + 2e-4f;
    }
    asm volatile("cp.async.wait_group 0;" ::: "memory");
    __syncthreads();

    float epsp[4];
    #pragma unroll
    for (int pi = 0; pi < 4; ++pi) epsp[pi] = epss[ty * 4 + pi];

    for (int ci = 0; ci < 16; ++ci) {
        if (ci + 1 < 16) {
            const char* es = reinterpret_cast<const char*>(g_e8) + (size_t)(ci + 1) * 32768;
            char* dst = sm + OFF_E + ((ci + 1) & 1) * 32768;
            #pragma unroll
            for (int i = 0; i < 8; ++i) {
                const int t = tid + i * 256;
                cpasync16(dst + t * 16, es + (size_t)t * 16);
            }
        }
        asm volatile("cp.async.commit_group;" ::: "memory");

        const uint32_t* Bp = E + (ci & 1) * 8192;
        int acc[32];
        #pragma unroll
        for (int i = 0; i < 32; ++i) acc[i] = 0;

        #pragma unroll 8
        for (int kw = 0; kw < 64; ++kw) {
            int4 a0 = *reinterpret_cast<const int4*>(Z + (kw << 7) + (ty << 2));       // pair0
            int4 a1 = *reinterpret_cast<const int4*>(Z + (kw << 7) + 64 + (ty << 2));  // pair1
            int4 b0 = *reinterpret_cast<const int4*>(Bp + (kw << 7) + (tx << 3));
            int4 b1 = *reinterpret_cast<const int4*>(Bp + (kw << 7) + (tx << 3) + 4);
            const int aa0[4] = {a0.x, a0.y, a0.z, a0.w};
            const int aa1[4] = {a1.x, a1.y, a1.z, a1.w};
            const int bb[8]  = {b0.x, b0.y, b0.z, b0.w, b1.x, b1.y, b1.z, b1.w};
            #pragma unroll
            for (int pi = 0; pi < 4; ++pi)
                #pragma unroll
                for (int cj = 0; cj < 8; ++cj) {
                    int a = __dp2a_lo(aa0[pi], bb[cj], acc[pi * 8 + cj]);
                    acc[pi * 8 + cj] = __dp2a_hi(aa1[pi], bb[cj], a);
                }
        }

        // epilogue: d = sume_j - 2*szg*se_j*acc ; per-pixel running min
        const int jc = ci << 7;
        float q8[8], se8[8];
        #pragma unroll
        for (int cj = 0; cj < 8; ++cj) {
            const int j = jc + (tx << 3) + cj;
            se8[cj] = __ldg(&g_sume[j]);
            q8[cj]  = -2.f * __ldg(&g_se[j]);
        }
        float rmin[4];
        #pragma unroll
        for (int pi = 0; pi < 4; ++pi) rmin[pi] = __int_as_float(0x7f800000);
        #pragma unroll
        for (int cj = 0; cj < 8; ++cj)
            #pragma unroll
            for (int pi = 0; pi < 4; ++pi) {
                float dd = fmaf((float)acc[pi * 8 + cj] * q8[cj], szg, se8[cj]);
                rmin[pi] = fminf(rmin[pi], dd);
            }
        #pragma unroll
        for (int off = 1; off <= 8; off <<= 1)
            #pragma unroll
            for (int pi = 0; pi < 4; ++pi)
                rmin[pi] = fminf(rmin[pi], __shfl_xor_sync(0xffffffffu, rmin[pi], off));
        if (tx == 0) {
            #pragma unroll
            for (int pi = 0; pi < 4; ++pi)
                atomicMin(&minU[ty * 4 + pi], encf(rmin[pi]));
        }
        __syncthreads();

        float thr[4];
        #pragma unroll
        for (int pi = 0; pi < 4; ++pi)
            thr[pi] = decf(minU[ty * 4 + pi]) + epsp[pi];
        #pragma unroll
        for (int cj = 0; cj < 8; ++cj)
            #pragma unroll
            for (int pi = 0; pi < 4; ++pi) {
                float dd = fmaf((float)acc[pi * 8 + cj] * q8[cj], szg, se8[cj]);
                if (dd <= thr[pi]) {
                    const int p = ty * 4 + pi;
                    int ix = atomicAdd(&cnt[p], 1);
                    if (ix < CAP) cand[p * CAP + ix] = jc + (tx << 3) + cj;
                }
            }

        asm volatile("cp.async.wait_group 0;" ::: "memory");
        __syncthreads();
    }

    if (tid < 64) {
        const int n = blk * 64 + tid;
        int c = cnt[tid];
        g_cnt[n] = c;
        if (c > CAP) c = CAP;
        for (int i = 0; i < c; ++i) g_cand[(size_t)n * CAP + i] = cand[tid * CAP + i];
    }
}

// ---------------------------------------------------------------------------
// refine: exact reference arithmetic on candidates -> g_idx
// ---------------------------------------------------------------------------
__device__ __forceinline__ void dot8(const float* __restrict__ z,
                                     const float* __restrict__ emb,
                                     size_t zbase, const int* ids,
                                     float* m, float& sz, bool do_sz) {
    #pragma unroll
    for (int i = 0; i < 8; ++i) m[i] = 0.f;
    for (int kc = 0; kc < 4; ++kc) {
        float zc[64];
        #pragma unroll
        for (int i = 0; i < 64; ++i)
            zc[i] = __ldg(&z[zbase + ((size_t)(kc * 64 + i) << 10)]);
        if (do_sz)
            #pragma unroll
            for (int i = 0; i < 64; ++i)
                sz = __fadd_rn(sz, __fmul_rn(zc[i], zc[i]));
        #pragma unroll
        for (int cd = 0; cd < 8; ++cd) {
            const float4* ep = reinterpret_cast<const float4*>(
                emb + (size_t)ids[cd] * DD + kc * 64);
            float mm = m[cd];
            #pragma unroll
            for (int q = 0; q < 16; ++q) {
                float4 e = __ldg(&ep[q]);
                mm = fmaf(zc[q * 4 + 0], e.x, mm);
                mm = fmaf(zc[q * 4 + 1], e.y, mm);
                mm = fmaf(zc[q * 4 + 2], e.z, mm);
                mm = fmaf(zc[q * 4 + 3], e.w, mm);
            }
            m[cd] = mm;
        }
    }
}

__global__ void __launch_bounds__(256) refine_kernel(const float* __restrict__ z,
                                                     const float* __restrict__ emb) {
    const int n = blockIdx.x * 256 + threadIdx.x;
    const int b = n >> 10, pix = n & 1023;
    const size_t zbase = ((size_t)b << 18) + pix;
    const int cnt = g_cnt[n];
    float best = __int_as_float(0x7f800000);
    int   bi = 0x7fffffff;
    float sz = 0.f;
    float m[8];
    int ids[8];

    if (cnt <= CAP) {
        for (int g0 = 0; g0 < cnt; g0 += 8) {
            #pragma unroll
            for (int i = 0; i < 8; ++i) {
                int q = g0 + i; if (q >= cnt) q = cnt - 1;
                ids[i] = g_cand[(size_t)n * CAP + q];
            }
            dot8(z, emb, zbase, ids, m, sz, g0 == 0);
            #pragma unroll
            for (int cd = 0; cd < 8; ++cd) {
                if (g0 + cd < cnt) {
                    int j = ids[cd];
                    float d = fmaf(m[cd], -2.f, __fadd_rn(sz, __ldg(&g_sume[j])));
                    if (d < best || (d == best && j < bi)) { best = d; bi = j; }
                }
            }
        }
    } else {
        for (int g0 = 0; g0 < KK; g0 += 8) {
            #pragma unroll
            for (int i = 0; i < 8; ++i) ids[i] = g0 + i;
            dot8(z, emb, zbase, ids, m, sz, g0 == 0);
            #pragma unroll
            for (int cd = 0; cd < 8; ++cd) {
                int j = g0 + cd;
                float d = fmaf(m[cd], -2.f, __fadd_rn(sz, __ldg(&g_sume[j])));
                if (d < best || (d == best && j < bi)) { best = d; bi = j; }
            }
        }
    }
    g_idx[n] = bi;
}

// ---------------------------------------------------------------------------
// quant: R1 version (measured 78us): gather + straight-through + loss
// ---------------------------------------------------------------------------
__global__ void __launch_bounds__(256)
quant_kernel(const float* __restrict__ z, const float* __restrict__ emb,
             float* __restrict__ out) {
    const size_t i = ((size_t)blockIdx.x * 256 + threadIdx.x) * 4;
    const int c = (int)((i >> 10) & 255);
    const int n = (int)(((i >> 18) << 10) | (i & 1023));

    int4   id4 = *reinterpret_cast<const int4*>(&g_idx[n]);
    float4 zp  = *reinterpret_cast<const float4*>(&z[i]);

    float e0 = __ldg(&emb[(size_t)id4.x * DD + c]);
    float e1 = __ldg(&emb[(size_t)id4.y * DD + c]);
    float e2 = __ldg(&emb[(size_t)id4.z * DD + c]);
    float e3 = __ldg(&emb[(size_t)id4.w * DD + c]);

    float t0 = __fsub_rn(e0, zp.x);
    float t1 = __fsub_rn(e1, zp.y);
    float t2 = __fsub_rn(e2, zp.z);
    float t3 = __fsub_rn(e3, zp.w);

    float4 o;
    o.x = __fadd_rn(zp.x, t0);
    o.y = __fadd_rn(zp.y, t1);
    o.z = __fadd_rn(zp.z, t2);
    o.w = __fadd_rn(zp.w, t3);
    *reinterpret_cast<float4*>(&out[i]) = o;

    double s = (double)__fmul_rn(t0, t0) + (double)__fmul_rn(t1, t1)
             + (double)__fmul_rn(t2, t2) + (double)__fmul_rn(t3, t3);

    #pragma unroll
    for (int off = 16; off; off >>= 1)
        s += __shfl_down_sync(0xffffffffu, s, off);
    __shared__ double ws[8];
    const int warp = threadIdx.x >> 5, lane = threadIdx.x & 31;
    if (lane == 0) ws[warp] = s;
    __syncthreads();
    if (threadIdx.x == 0) {
        double t = 0.0;
        #pragma unroll
        for (int w = 0; w < 8; ++w) t += ws[w];
        atomicAdd(&g_loss, t);
    }
}

// ---------------------------------------------------------------------------
__global__ void write_extras_kernel(float* __restrict__ out, int out_size) {
    const int t = blockIdx.x * 256 + threadIdx.x;
    if (out_size == NN) { if (t < NN) out[t] = (float)g_idx[t]; return; }
    const int rem = out_size - ZQ;
    if (rem >= NN && t < NN) out[ZQ + t] = (float)g_idx[t];
    if (rem >= NN + 1 && t == 0) {
        float m = (float)(g_loss * (1.0 / 16777216.0));
        out[ZQ + NN] = __fadd_rn(m, __fmul_rn(0.25f, m));
    }
    if (rem >= 2 * NN + 1 && t < NN) out[ZQ + NN + 1 + t] = (float)g_idx[t];
}

// ---------------------------------------------------------------------------
extern "C" void kernel_launch(void* const* d_in, const int* in_sizes, int n_in,
                              void* d_out, int out_size) {
    const float* z;
    const float* emb;
    if (in_sizes[0] == ZQ) { z = (const float*)d_in[0]; emb = (const float*)d_in[1]; }
    else                   { z = (const float*)d_in[1]; emb = (const float*)d_in[0]; }
    float* out = (float*)d_out;

    cudaFuncSetAttribute(assign_dp2a,
                         cudaFuncAttributeMaxDynamicSharedMemorySize, ASMEM);

    init_kernel<<<1, 1>>>();
    zmax_kernel<<<1024, 256>>>(z);
    prep_e8<<<8, 256>>>(emb);
    assign_dp2a<<<1024, 256, ASMEM>>>(z);
    refine_kernel<<<256, 256>>>(z, emb);
    if (out_size >= ZQ)
        quant_kernel<<<(NN * DD) / (256 * 4), 256>>>(z, emb, out);
    if (out_size > ZQ || out_size == NN)
        write_extras_kernel<<<NN / 256, 256>>>(out, out_size);
}